// round 3
// baseline (speedup 1.0000x reference)
#include <cuda_runtime.h>
#include <cstdint>

#define NSAMP 256000
#define BATCH 64
#define TT 997
#define BT (BATCH * TT)   // 63808
#define NFREQ 513
#define ENCD 256
#define EPS32 1.1920928955078125e-07f
#define PI_F 3.14159265358979323846f

// ---------------- scratch (device globals; allocation-free rule) ----------------
__device__ float g_mag [(size_t)BT * NFREQ];
__device__ float g_Rm  [(size_t)BT * NFREQ];
__device__ float g_Imb [(size_t)BT * NFREQ];
__device__ float g_xg  [(size_t)BT * 512];
__device__ float g_h1  [(size_t)BT * 128];
__device__ float g_h2  [(size_t)BT * 128];
__device__ float g_mask1[(size_t)BT * NFREQ];
__device__ float g_y1  [(size_t)BT * 1024];
__device__ float g_enc [(size_t)BT * ENCD];
__device__ float g_encn[(size_t)BT * ENCD];
__device__ float g_m2e [(size_t)BT * ENCD];
__device__ float g_dec [(size_t)BT * 1024];

__device__ __forceinline__ float sigm(float x) { return 1.0f / (1.0f + __expf(-x)); }
__device__ __forceinline__ float tanh_f(float x) { return 2.0f / (1.0f + __expf(-2.0f * x)) - 1.0f; }

// ---------------- 512-pt complex Stockham FFT in shared memory ----------------
// sign = -1 forward, +1 inverse (unnormalized). 256 threads, 1 butterfly each/stage.
__device__ __forceinline__ float2* fft512(float2* a, float2* b, float sign, int tid) {
    float2* src = a; float2* dst = b;
    #pragma unroll
    for (int s = 0; s < 9; s++) {
        int m = 1 << s;
        int l = 256 >> s;
        int j = tid >> s;
        int k = tid & (m - 1);
        float coef = sign * PI_F / (float)l;
        float2 c0 = src[tid];
        float2 c1 = src[tid + 256];
        float ws, wc;
        __sincosf(coef * (float)j, &ws, &wc);
        float2 dif = make_float2(c0.x - c1.x, c0.y - c1.y);
        dst[2 * j * m + k]     = make_float2(c0.x + c1.x, c0.y + c1.y);
        dst[2 * j * m + k + m] = make_float2(wc * dif.x - ws * dif.y, wc * dif.y + ws * dif.x);
        __syncthreads();
        float2* t = src; src = dst; dst = t;
    }
    return src;
}

// ---------------- STFT: frames -> mag, mag*cos(phase), mag*sin(phase) ----------------
__global__ void stft_kernel(const float* __restrict__ x, float* __restrict__ mag,
                            float* __restrict__ Rm, float* __restrict__ Imb) {
    __shared__ float2 za[512], zb[512];
    int bt = blockIdx.x;
    int b = bt / TT, t = bt - b * TT;
    const float* xp = x + (size_t)b * NSAMP + t * 256;
    int tid = threadIdx.x;
    for (int n = tid; n < 512; n += 256) {
        float w0 = 0.5f * (1.0f - cospif((float)(2 * n)     * (1.0f / 512.0f)));
        float w1 = 0.5f * (1.0f - cospif((float)(2 * n + 1) * (1.0f / 512.0f)));
        za[n] = make_float2(xp[2 * n] * w0, xp[2 * n + 1] * w1);
    }
    __syncthreads();
    float2* Z = fft512(za, zb, -1.0f, tid);
    size_t base = (size_t)bt * NFREQ;
    for (int k = tid; k <= 512; k += 256) {
        float2 zk = Z[k & 511];
        float2 zc = Z[(512 - k) & 511];
        float Er = 0.5f * (zk.x + zc.x), Ei = 0.5f * (zk.y - zc.y);
        float Or = 0.5f * (zk.y + zc.y), Oi = -0.5f * (zk.x - zc.x);
        float ws, wc;
        __sincosf(-PI_F * (float)k * (1.0f / 512.0f), &ws, &wc);
        float Xr = Er + wc * Or - ws * Oi;
        float Xi = Ei + wc * Oi + ws * Or;
        float mg = sqrtf(fmaxf(Xr * Xr + Xi * Xi, EPS32));
        float rp = Xr + EPS32, ip = Xi + EPS32;
        float inv = rsqrtf(rp * rp + ip * ip);
        mag[base + k] = mg;
        Rm[base + k]  = mg * rp * inv;
        Imb[base + k] = mg * ip * inv;
    }
}

// ---------------- masked iSTFT: mask1*(Rm+i*Im) -> irfft(1024) ----------------
__global__ void ifft_kernel(const float* __restrict__ mask, const float* __restrict__ Rm,
                            const float* __restrict__ Imb, float* __restrict__ y) {
    __shared__ float2 Xs[513];
    __shared__ float2 za[512], zb[512];
    int bt = blockIdx.x;
    int tid = threadIdx.x;
    size_t base = (size_t)bt * NFREQ;
    for (int k = tid; k <= 512; k += 256) {
        float mk = mask[base + k];
        Xs[k] = make_float2(mk * Rm[base + k], mk * Imb[base + k]);
    }
    __syncthreads();
    for (int k = tid; k < 512; k += 256) {
        float2 xk = Xs[k];
        float2 xc = Xs[512 - k];
        float Ar = 0.5f * (xk.x + xc.x), Ai = 0.5f * (xk.y - xc.y);
        float Br = 0.5f * (xk.x - xc.x), Bi = 0.5f * (xk.y + xc.y);
        float ws, wc;
        __sincosf(PI_F * (float)k * (1.0f / 512.0f), &ws, &wc);
        float B2r = wc * Br - ws * Bi;
        float B2i = wc * Bi + ws * Br;
        za[k] = make_float2(Ar - B2i, Ai + B2r);
    }
    __syncthreads();
    float2* Zr = fft512(za, zb, 1.0f, tid);
    float* yp = y + (size_t)bt * 1024;
    const float scale = 1.0f / 512.0f;
    for (int n = tid; n < 512; n += 256) {
        yp[2 * n]     = Zr[n].x * scale;
        yp[2 * n + 1] = Zr[n].y * scale;
    }
}

// ---------------- generic NT GEMM: C[M,N] = A[M,K] @ W[N,K]^T (+epilogue) ----------------
// MODE 0: + b1 + b2 (nullable). MODE 1: sigmoid(+b1). MODE 2: sigmoid(+b1)*aux[m,n].
template<int MODE>
__global__ void __launch_bounds__(256) gemm_nt(
    const float* __restrict__ A, const float* __restrict__ W,
    const float* __restrict__ b1, const float* __restrict__ b2,
    const float* __restrict__ aux, float* __restrict__ C,
    int M, int N, int K) {
    __shared__ float As[16][128];
    __shared__ float Bs[16][128];
    int tid = threadIdx.x;
    int tx = tid & 15, ty = tid >> 4;
    int m0 = blockIdx.x * 128, n0 = blockIdx.y * 128;
    int lr = tid >> 1;          // row/col within tile for loading
    int lh = (tid & 1) * 8;     // k-offset half
    float acc[8][8];
    #pragma unroll
    for (int i = 0; i < 8; i++)
        #pragma unroll
        for (int j = 0; j < 8; j++) acc[i][j] = 0.0f;
    int am = m0 + lr;
    int bn = n0 + lr;
    bool av = am < M, bv = bn < N;
    const float* Arow = A + (size_t)(av ? am : 0) * K;
    const float* Wrow = W + (size_t)(bv ? bn : 0) * K;
    for (int k0 = 0; k0 < K; k0 += 16) {
        #pragma unroll
        for (int j = 0; j < 8; j++) {
            int k = k0 + lh + j;
            As[lh + j][lr] = (av && k < K) ? Arow[k] : 0.0f;
            Bs[lh + j][lr] = (bv && k < K) ? Wrow[k] : 0.0f;
        }
        __syncthreads();
        #pragma unroll
        for (int kk = 0; kk < 16; kk++) {
            float a[8], bb[8];
            *(float4*)(a)      = *(const float4*)&As[kk][ty * 8];
            *(float4*)(a + 4)  = *(const float4*)&As[kk][ty * 8 + 4];
            *(float4*)(bb)     = *(const float4*)&Bs[kk][tx * 8];
            *(float4*)(bb + 4) = *(const float4*)&Bs[kk][tx * 8 + 4];
            #pragma unroll
            for (int i = 0; i < 8; i++)
                #pragma unroll
                for (int j = 0; j < 8; j++) acc[i][j] += a[i] * bb[j];
        }
        __syncthreads();
    }
    #pragma unroll
    for (int i = 0; i < 8; i++) {
        int m = m0 + ty * 8 + i;
        if (m >= M) continue;
        #pragma unroll
        for (int j = 0; j < 8; j++) {
            int n = n0 + tx * 8 + j;
            if (n >= N) continue;
            float v = acc[i][j];
            if (MODE == 0) {
                if (b1) v += __ldg(&b1[n]);
                if (b2) v += __ldg(&b2[n]);
            } else if (MODE == 1) {
                v = sigm(v + __ldg(&b1[n]));
            } else {
                v = sigm(v + __ldg(&b1[n])) * aux[(size_t)m * N + n];
            }
            C[(size_t)m * N + n] = v;
        }
    }
}

// ---------------- LSTM scan: one CTA per batch elem, thread r = gate row r ----------------
// Whh cols 0..63 in registers (fp32), cols 64..127 in smem (transposed, conflict-free).
__global__ void __launch_bounds__(512) lstm_kernel(
    const float* __restrict__ xg, float* __restrict__ hout,
    const float* __restrict__ Whh, const float* __restrict__ state, int layer) {
    extern __shared__ float sm[];
    float* Wsm = sm;              // [64][512] transposed: Wsm[c*512+r] = Whh[r][64+c]
    float* h_s = sm + 64 * 512;   // 128
    float* g_s = h_s + 128;       // 512
    int b = blockIdx.x, r = threadIdx.x;
    float w[64];
    #pragma unroll
    for (int j = 0; j < 64; j++) w[j] = Whh[r * 128 + j];
    for (int idx = r; idx < 64 * 512; idx += 512) {
        int rr = idx >> 6, c = idx & 63;
        Wsm[c * 512 + rr] = Whh[rr * 128 + 64 + c];
    }
    float cv = 0.0f;
    if (r < 128) {
        size_t sb = ((size_t)(layer * BATCH + b) * 128 + r) * 2;
        h_s[r] = state[sb];
        cv     = state[sb + 1];
    }
    __syncthreads();
    const float* xr = xg + (size_t)b * TT * 512;
    float* hr = hout + (size_t)b * TT * 128;
    for (int t = 0; t < TT; t++) {
        float acc = xr[t * 512 + r];
        #pragma unroll
        for (int j = 0; j < 64; j += 4) {
            float4 h4 = *(const float4*)&h_s[j];
            acc += w[j] * h4.x + w[j + 1] * h4.y + w[j + 2] * h4.z + w[j + 3] * h4.w;
        }
        #pragma unroll
        for (int j = 0; j < 64; j += 4) {
            float4 h4 = *(const float4*)&h_s[64 + j];
            acc += Wsm[j * 512 + r] * h4.x + Wsm[(j + 1) * 512 + r] * h4.y
                 + Wsm[(j + 2) * 512 + r] * h4.z + Wsm[(j + 3) * 512 + r] * h4.w;
        }
        g_s[r] = acc;
        __syncthreads();
        if (r < 128) {
            float iv = sigm(g_s[r]);
            float fv = sigm(g_s[128 + r]);
            float gv = tanh_f(g_s[256 + r]);
            float ov = sigm(g_s[384 + r]);
            cv = fv * cv + iv * gv;
            float hv = ov * tanh_f(cv);
            h_s[r] = hv;
            hr[t * 128 + r] = hv;
        }
        __syncthreads();
    }
}

// ---------------- instant layernorm over last dim (256) ----------------
__global__ void iln_kernel(const float* __restrict__ enc, const float* __restrict__ gamma,
                           const float* __restrict__ beta, float* __restrict__ out) {
    int bt = blockIdx.x, tid = threadIdx.x;  // 256 threads
    float v = enc[(size_t)bt * ENCD + tid];
    float s1 = v, s2 = v * v;
    #pragma unroll
    for (int o = 16; o > 0; o >>= 1) {
        s1 += __shfl_xor_sync(0xffffffff, s1, o);
        s2 += __shfl_xor_sync(0xffffffff, s2, o);
    }
    __shared__ float r1[8], r2[8];
    int wid = tid >> 5;
    if ((tid & 31) == 0) { r1[wid] = s1; r2[wid] = s2; }
    __syncthreads();
    if (tid == 0) {
        float a1 = 0.0f, a2 = 0.0f;
        #pragma unroll
        for (int i = 0; i < 8; i++) { a1 += r1[i]; a2 += r2[i]; }
        r1[0] = a1; r2[0] = a2;
    }
    __syncthreads();
    float mean = r1[0] * (1.0f / 256.0f);
    float var  = r2[0] * (1.0f / 256.0f) - mean * mean;
    out[(size_t)bt * ENCD + tid] =
        (v - mean) * rsqrtf(var + 1e-7f) * gamma[tid] + beta[tid];
}

// ---------------- overlap-add ----------------
__global__ void ola_kernel(const float* __restrict__ dec, float* __restrict__ out) {
    int s = blockIdx.x * 256 + threadIdx.x;
    int b = blockIdx.y;
    int thi = min(TT - 1, s >> 8);
    int tlo = (s >= 1024) ? ((s - 1023 + 255) >> 8) : 0;
    float acc = 0.0f;
    for (int t = tlo; t <= thi; t++)
        acc += dec[((size_t)b * TT + t) * 1024 + (s - (t << 8))];
    out[(size_t)b * NSAMP + s] = acc;
}

// ---------------- host ----------------
extern "C" void kernel_launch(void* const* d_in, const int* in_sizes, int n_in,
                              void* d_out, int out_size) {
    const float* x        = (const float*)d_in[0];
    const float* st1      = (const float*)d_in[1];
    const float* st2      = (const float*)d_in[2];
    const float* s1_Wih1  = (const float*)d_in[3];
    const float* s1_Whh1  = (const float*)d_in[4];
    const float* s1_bih1  = (const float*)d_in[5];
    const float* s1_bhh1  = (const float*)d_in[6];
    const float* s1_Wih2  = (const float*)d_in[7];
    const float* s1_Whh2  = (const float*)d_in[8];
    const float* s1_bih2  = (const float*)d_in[9];
    const float* s1_bhh2  = (const float*)d_in[10];
    const float* s1_Wd    = (const float*)d_in[11];
    const float* s1_bd    = (const float*)d_in[12];
    const float* s2_Wih1  = (const float*)d_in[13];
    const float* s2_Whh1  = (const float*)d_in[14];
    const float* s2_bih1  = (const float*)d_in[15];
    const float* s2_bhh1  = (const float*)d_in[16];
    const float* s2_Wih2  = (const float*)d_in[17];
    const float* s2_Whh2  = (const float*)d_in[18];
    const float* s2_bih2  = (const float*)d_in[19];
    const float* s2_bhh2  = (const float*)d_in[20];
    const float* s2_Wd    = (const float*)d_in[21];
    const float* s2_bd    = (const float*)d_in[22];
    const float* enc_W    = (const float*)d_in[23];
    const float* dec_W    = (const float*)d_in[24];
    const float* gamma    = (const float*)d_in[25];
    const float* beta     = (const float*)d_in[26];
    float* out = (float*)d_out;

    float *mag, *Rm, *Imb, *xg, *h1, *h2, *mask1, *y1, *enc, *encn, *m2e, *dec;
    cudaGetSymbolAddress((void**)&mag,   g_mag);
    cudaGetSymbolAddress((void**)&Rm,    g_Rm);
    cudaGetSymbolAddress((void**)&Imb,   g_Imb);
    cudaGetSymbolAddress((void**)&xg,    g_xg);
    cudaGetSymbolAddress((void**)&h1,    g_h1);
    cudaGetSymbolAddress((void**)&h2,    g_h2);
    cudaGetSymbolAddress((void**)&mask1, g_mask1);
    cudaGetSymbolAddress((void**)&y1,    g_y1);
    cudaGetSymbolAddress((void**)&enc,   g_enc);
    cudaGetSymbolAddress((void**)&encn,  g_encn);
    cudaGetSymbolAddress((void**)&m2e,   g_m2e);
    cudaGetSymbolAddress((void**)&dec,   g_dec);

    const int LSTM_SMEM = (64 * 512 + 128 + 512) * 4;  // 133,632 B
    cudaFuncSetAttribute(lstm_kernel, cudaFuncAttributeMaxDynamicSharedMemorySize, LSTM_SMEM);

    const int MT = (BT + 127) / 128;  // 499

    // ---- STFT ----
    stft_kernel<<<BT, 256>>>(x, mag, Rm, Imb);

    // ---- separation block 1 (on magnitude) ----
    gemm_nt<0><<<dim3(MT, 4), 256>>>(mag, s1_Wih1, s1_bih1, s1_bhh1, nullptr, xg, BT, 512, NFREQ);
    lstm_kernel<<<BATCH, 512, LSTM_SMEM>>>(xg, h1, s1_Whh1, st1, 0);
    gemm_nt<0><<<dim3(MT, 4), 256>>>(h1, s1_Wih2, s1_bih2, s1_bhh2, nullptr, xg, BT, 512, 128);
    lstm_kernel<<<BATCH, 512, LSTM_SMEM>>>(xg, h2, s1_Whh2, st1, 1);
    gemm_nt<1><<<dim3(MT, 5), 256>>>(h2, s1_Wd, s1_bd, nullptr, nullptr, mask1, BT, NFREQ, 128);

    // ---- masked iSTFT ----
    ifft_kernel<<<BT, 256>>>(mask1, Rm, Imb, y1);

    // ---- encoder + instant LN ----
    gemm_nt<0><<<dim3(MT, 2), 256>>>(y1, enc_W, nullptr, nullptr, nullptr, enc, BT, ENCD, 1024);
    iln_kernel<<<BT, 256>>>(enc, gamma, beta, encn);

    // ---- separation block 2 (on normalized encoding) ----
    gemm_nt<0><<<dim3(MT, 4), 256>>>(encn, s2_Wih1, s2_bih1, s2_bhh1, nullptr, xg, BT, 512, ENCD);
    lstm_kernel<<<BATCH, 512, LSTM_SMEM>>>(xg, h1, s2_Whh1, st2, 0);
    gemm_nt<0><<<dim3(MT, 4), 256>>>(h1, s2_Wih2, s2_bih2, s2_bhh2, nullptr, xg, BT, 512, 128);
    lstm_kernel<<<BATCH, 512, LSTM_SMEM>>>(xg, h2, s2_Whh2, st2, 1);
    gemm_nt<2><<<dim3(MT, 2), 256>>>(h2, s2_Wd, s2_bd, nullptr, enc, m2e, BT, ENCD, 128);

    // ---- decoder + overlap-add ----
    gemm_nt<0><<<dim3(MT, 8), 256>>>(m2e, dec_W, nullptr, nullptr, nullptr, dec, BT, 1024, ENCD);
    ola_kernel<<<dim3(NSAMP / 256, BATCH), 256>>>(dec, out);
}

// round 6
// speedup vs baseline: 1.2250x; 1.2250x over previous
#include <cuda_runtime.h>
#include <cstdint>

#define NSAMP 256000
#define BATCH 64
#define TT 997
#define BT (BATCH * TT)   // 63808
#define NFREQ 513
#define MAGP 528          // mag padded stride (33*16)
#define ENCD 256
#define EPS32 1.1920928955078125e-07f
#define PI_F 3.14159265358979323846f

// ---------------- scratch (device globals; allocation-free rule) ----------------
__device__ float g_mag [(size_t)BT * MAGP];
__device__ float g_Rm  [(size_t)BT * NFREQ];
__device__ float g_Imb [(size_t)BT * NFREQ];
__device__ float g_xg  [(size_t)BT * 512];
__device__ float g_h1  [(size_t)BT * 128];
__device__ float g_h2  [(size_t)BT * 128];
__device__ float g_mask1[(size_t)BT * NFREQ];
__device__ float g_y1  [(size_t)BT * 1024];
__device__ float g_enc [(size_t)BT * ENCD];
__device__ float g_encn[(size_t)BT * ENCD];
__device__ float g_m2e [(size_t)BT * ENCD];
__device__ float g_dec [(size_t)BT * 1024];
__device__ float g_w1p [512 * MAGP];

__device__ __forceinline__ float sigm(float x) { return 1.0f / (1.0f + __expf(-x)); }
__device__ __forceinline__ float tanh_f(float x) { return 2.0f / (1.0f + __expf(-2.0f * x)) - 1.0f; }

// ---------------- cp.async helpers ----------------
__device__ __forceinline__ void cp16(uint32_t dst, const void* src) {
    asm volatile("cp.async.cg.shared.global [%0], [%1], 16;" :: "r"(dst), "l"(src));
}
#define CP_COMMIT() asm volatile("cp.async.commit_group;" ::: "memory")
#define CP_WAIT(n)  asm volatile("cp.async.wait_group %0;" :: "n"(n) : "memory")

// ---------------- 3xTF32 split: f = hi + lo, both tf32 (rna) ----------------
__device__ __forceinline__ void tf32split(float f, uint32_t& hi, uint32_t& lo) {
    uint32_t h;
    asm("cvt.rna.tf32.f32 %0, %1;" : "=r"(h) : "f"(f));
    float r = f - __uint_as_float(h);
    asm("cvt.rna.tf32.f32 %0, %1;" : "=r"(lo) : "f"(r));
    hi = h;
}
__device__ __forceinline__ void mma8(float* c, const uint32_t* a, const uint32_t* b) {
    asm volatile(
        "mma.sync.aligned.m16n8k8.row.col.f32.tf32.tf32.f32 "
        "{%0,%1,%2,%3}, {%4,%5,%6,%7}, {%8,%9}, {%0,%1,%2,%3};"
        : "+f"(c[0]), "+f"(c[1]), "+f"(c[2]), "+f"(c[3])
        : "r"(a[0]), "r"(a[1]), "r"(a[2]), "r"(a[3]), "r"(b[0]), "r"(b[1]));
}

// ---------------- 3xTF32 tensor-core GEMM: C[M,N] = A[M,K] @ W[N,K]^T ----------------
// MODE 0: + b1 + b2 (nullable). MODE 1: sigmoid(+b1). MODE 2: sigmoid(+b1)*aux[m,n].
// Tile 128x128x16, 8 warps (4x2), warp tile 32x64, mma.m16n8k8 tf32 x3 (error comp).
// Requires K % 16 == 0.
#define SSTRIDE 20   // floats per smem row (conflict-free for quad pattern + 16B aligned)
template<int MODE>
__global__ void __launch_bounds__(256) gemm_mma(
    const float* __restrict__ A, const float* __restrict__ W,
    const float* __restrict__ b1, const float* __restrict__ b2,
    const float* __restrict__ aux, float* __restrict__ C,
    int M, int N, int K, int lda, int ldw, int ldc)
{
    __shared__ float As[2][128 * SSTRIDE];
    __shared__ float Bs[2][128 * SSTRIDE];
    int tid = threadIdx.x;
    int lane = tid & 31;
    int wid = tid >> 5;
    int wm = wid & 3;           // warp row (4)
    int wn = wid >> 2;          // warp col (2)
    int m0 = blockIdx.x * 128, n0 = blockIdx.y * 128;

    // loader mapping: row = tid/2, two 16B chunks at (tid&1)*2 + {0,1}
    int lr = tid >> 1;
    int lc0 = (tid & 1) * 2;
    const float* Arow = A + (size_t)min(m0 + lr, M - 1) * lda;
    const float* Wrow = W + (size_t)min(n0 + lr, N - 1) * ldw;

    uint32_t sA0 = (uint32_t)__cvta_generic_to_shared(&As[0][0]);
    uint32_t sB0 = (uint32_t)__cvta_generic_to_shared(&Bs[0][0]);
    const uint32_t stageBytes = 128 * SSTRIDE * 4;
    uint32_t dstOffA = (lr * SSTRIDE + lc0 * 4) * 4;

    #define LOAD_STAGE(t, s) do { \
        uint32_t dA = sA0 + (s) * stageBytes + dstOffA; \
        uint32_t dB = sB0 + (s) * stageBytes + dstOffA; \
        int f0 = (t) * 16 + lc0 * 4; \
        cp16(dA,      Arow + f0); \
        cp16(dA + 16, Arow + f0 + 4); \
        cp16(dB,      Wrow + f0); \
        cp16(dB + 16, Wrow + f0 + 4); \
        CP_COMMIT(); \
    } while (0)

    float c[2][8][4];
    #pragma unroll
    for (int mi = 0; mi < 2; mi++)
        #pragma unroll
        for (int j = 0; j < 8; j++)
            #pragma unroll
            for (int r = 0; r < 4; r++) c[mi][j][r] = 0.0f;

    const int NT = K >> 4;
    LOAD_STAGE(0, 0);

    // fragment base offsets (floats)
    int aoff0 = (wm * 32 + (lane >> 2)) * SSTRIDE + (lane & 3);
    int boff0 = (wn * 64 + (lane >> 2)) * SSTRIDE + (lane & 3);

    for (int t = 0; t < NT; t++) {
        int buf = t & 1;
        if (t + 1 < NT) {
            LOAD_STAGE(t + 1, (t + 1) & 1);
            CP_WAIT(1);
        } else {
            CP_WAIT(0);
        }
        __syncthreads();

        const float* Sa = As[buf];
        const float* Sb = Bs[buf];
        #pragma unroll
        for (int kh = 0; kh < 2; kh++) {
            uint32_t ah[2][4], al[2][4];
            #pragma unroll
            for (int mi = 0; mi < 2; mi++) {
                int o = aoff0 + mi * 16 * SSTRIDE + kh * 8;
                tf32split(Sa[o],                   ah[mi][0], al[mi][0]);
                tf32split(Sa[o + 8 * SSTRIDE],     ah[mi][1], al[mi][1]);
                tf32split(Sa[o + 4],               ah[mi][2], al[mi][2]);
                tf32split(Sa[o + 8 * SSTRIDE + 4], ah[mi][3], al[mi][3]);
            }
            uint32_t bh[8][2], bl[8][2];
            #pragma unroll
            for (int j = 0; j < 8; j++) {
                int o = boff0 + j * 8 * SSTRIDE + kh * 8;
                tf32split(Sb[o],     bh[j][0], bl[j][0]);
                tf32split(Sb[o + 4], bh[j][1], bl[j][1]);
            }
            #pragma unroll
            for (int mi = 0; mi < 2; mi++)
                #pragma unroll
                for (int j = 0; j < 8; j++) {
                    mma8(c[mi][j], ah[mi], bl[j]);   // hi*lo
                    mma8(c[mi][j], al[mi], bh[j]);   // lo*hi
                    mma8(c[mi][j], ah[mi], bh[j]);   // hi*hi
                }
        }
        __syncthreads();
    }

    // epilogue: c0/c1 -> (row, 2q), (row, 2q+1); c2/c3 -> row+8
    #pragma unroll
    for (int mi = 0; mi < 2; mi++) {
        #pragma unroll
        for (int rh = 0; rh < 2; rh++) {
            int m = m0 + wm * 32 + mi * 16 + (lane >> 2) + rh * 8;
            if (m >= M) continue;
            float* crow = C + (size_t)m * ldc;
            const float* arow = (MODE == 2) ? aux + (size_t)m * ldc : nullptr;
            #pragma unroll
            for (int j = 0; j < 8; j++) {
                int n = n0 + wn * 64 + j * 8 + 2 * (lane & 3);
                float v0 = c[mi][j][rh * 2];
                float v1 = c[mi][j][rh * 2 + 1];
                if (MODE == 0) {
                    if (b1) { v0 += __ldg(&b1[n]); v1 += __ldg(&b1[n + 1]); }
                    if (b2) { v0 += __ldg(&b2[n]); v1 += __ldg(&b2[n + 1]); }
                    if (n < N)     crow[n]     = v0;
                    if (n + 1 < N) crow[n + 1] = v1;
                } else if (MODE == 1) {
                    if (n < N)     crow[n]     = sigm(v0 + __ldg(&b1[n]));
                    if (n + 1 < N) crow[n + 1] = sigm(v1 + __ldg(&b1[n + 1]));
                } else {
                    if (n < N)     crow[n]     = sigm(v0 + __ldg(&b1[n]))     * arow[n];
                    if (n + 1 < N) crow[n + 1] = sigm(v1 + __ldg(&b1[n + 1])) * arow[n + 1];
                }
            }
        }
    }
    #undef LOAD_STAGE
}

// ---------------- weight pack: s1_Wih1 [512,513] -> [512,528] zero-padded ----------------
__global__ void pack_w1(const float* __restrict__ w, float* __restrict__ out) {
    int i = blockIdx.x * 256 + threadIdx.x;
    if (i < 512 * MAGP) {
        int r = i / MAGP, c = i - r * MAGP;
        out[i] = (c < NFREQ) ? w[r * NFREQ + c] : 0.0f;
    }
}

// ---------------- 512-pt complex Stockham FFT in shared memory ----------------
__device__ __forceinline__ float2* fft512(float2* a, float2* b, float sign, int tid) {
    float2* src = a; float2* dst = b;
    #pragma unroll
    for (int s = 0; s < 9; s++) {
        int m = 1 << s;
        int l = 256 >> s;
        int j = tid >> s;
        int k = tid & (m - 1);
        float coef = sign * PI_F / (float)l;
        float2 c0 = src[tid];
        float2 c1 = src[tid + 256];
        float ws, wc;
        __sincosf(coef * (float)j, &ws, &wc);
        float2 dif = make_float2(c0.x - c1.x, c0.y - c1.y);
        dst[2 * j * m + k]     = make_float2(c0.x + c1.x, c0.y + c1.y);
        dst[2 * j * m + k + m] = make_float2(wc * dif.x - ws * dif.y, wc * dif.y + ws * dif.x);
        __syncthreads();
        float2* t = src; src = dst; dst = t;
    }
    return src;
}

// ---------------- STFT: frames -> mag (stride MAGP, zero-padded), Rm, Im ----------------
__global__ void stft_kernel(const float* __restrict__ x, float* __restrict__ mag,
                            float* __restrict__ Rm, float* __restrict__ Imb) {
    __shared__ float2 za[512], zb[512];
    int bt = blockIdx.x;
    int b = bt / TT, t = bt - b * TT;
    const float* xp = x + (size_t)b * NSAMP + t * 256;
    int tid = threadIdx.x;
    for (int n = tid; n < 512; n += 256) {
        float w0 = 0.5f * (1.0f - cospif((float)(2 * n)     * (1.0f / 512.0f)));
        float w1 = 0.5f * (1.0f - cospif((float)(2 * n + 1) * (1.0f / 512.0f)));
        za[n] = make_float2(xp[2 * n] * w0, xp[2 * n + 1] * w1);
    }
    __syncthreads();
    float2* Z = fft512(za, zb, -1.0f, tid);
    size_t baseM = (size_t)bt * MAGP;
    size_t base = (size_t)bt * NFREQ;
    for (int k = tid; k <= 512; k += 256) {
        float2 zk = Z[k & 511];
        float2 zc = Z[(512 - k) & 511];
        float Er = 0.5f * (zk.x + zc.x), Ei = 0.5f * (zk.y - zc.y);
        float Or = 0.5f * (zk.y + zc.y), Oi = -0.5f * (zk.x - zc.x);
        float ws, wc;
        __sincosf(-PI_F * (float)k * (1.0f / 512.0f), &ws, &wc);
        float Xr = Er + wc * Or - ws * Oi;
        float Xi = Ei + wc * Oi + ws * Or;
        float mg = sqrtf(fmaxf(Xr * Xr + Xi * Xi, EPS32));
        float rp = Xr + EPS32, ip = Xi + EPS32;
        float inv = rsqrtf(rp * rp + ip * ip);
        mag[baseM + k] = mg;
        Rm[base + k]   = mg * rp * inv;
        Imb[base + k]  = mg * ip * inv;
    }
    if (tid < MAGP - NFREQ) mag[baseM + NFREQ + tid] = 0.0f;  // zero K padding
}

// ---------------- masked iSTFT ----------------
__global__ void ifft_kernel(const float* __restrict__ mask, const float* __restrict__ Rm,
                            const float* __restrict__ Imb, float* __restrict__ y) {
    __shared__ float2 Xs[513];
    __shared__ float2 za[512], zb[512];
    int bt = blockIdx.x;
    int tid = threadIdx.x;
    size_t base = (size_t)bt * NFREQ;
    for (int k = tid; k <= 512; k += 256) {
        float mk = mask[base + k];
        Xs[k] = make_float2(mk * Rm[base + k], mk * Imb[base + k]);
    }
    __syncthreads();
    for (int k = tid; k < 512; k += 256) {
        float2 xk = Xs[k];
        float2 xc = Xs[512 - k];
        float Ar = 0.5f * (xk.x + xc.x), Ai = 0.5f * (xk.y - xc.y);
        float Br = 0.5f * (xk.x - xc.x), Bi = 0.5f * (xk.y + xc.y);
        float ws, wc;
        __sincosf(PI_F * (float)k * (1.0f / 512.0f), &ws, &wc);
        float B2r = wc * Br - ws * Bi;
        float B2i = wc * Bi + ws * Br;
        za[k] = make_float2(Ar - B2i, Ai + B2r);
    }
    __syncthreads();
    float2* Zr = fft512(za, zb, 1.0f, tid);
    float* yp = y + (size_t)bt * 1024;
    const float scale = 1.0f / 512.0f;
    for (int n = tid; n < 512; n += 256) {
        yp[2 * n]     = Zr[n].x * scale;
        yp[2 * n + 1] = Zr[n].y * scale;
    }
}

// ---------------- LSTM scan: one CTA per batch elem, thread r = gate row r ----------------
__global__ void __launch_bounds__(512) lstm_kernel(
    const float* __restrict__ xg, float* __restrict__ hout,
    const float* __restrict__ Whh, const float* __restrict__ state, int layer) {
    extern __shared__ float sm[];
    float* Wsm = sm;              // [64][512] transposed: Wsm[c*512+r] = Whh[r][64+c]
    float* h_s = sm + 64 * 512;   // 128
    float* g_s = h_s + 128;       // 512
    int b = blockIdx.x, r = threadIdx.x;
    float w[64];
    #pragma unroll
    for (int j = 0; j < 64; j++) w[j] = Whh[r * 128 + j];
    for (int idx = r; idx < 64 * 512; idx += 512) {
        int rr = idx >> 6, c = idx & 63;
        Wsm[c * 512 + rr] = Whh[rr * 128 + 64 + c];
    }
    float cv = 0.0f;
    if (r < 128) {
        size_t sb = ((size_t)(layer * BATCH + b) * 128 + r) * 2;
        h_s[r] = state[sb];
        cv     = state[sb + 1];
    }
    __syncthreads();
    const float* xr = xg + (size_t)b * TT * 512;
    float* hr = hout + (size_t)b * TT * 128;
    for (int t = 0; t < TT; t++) {
        float acc = xr[t * 512 + r];
        #pragma unroll
        for (int j = 0; j < 64; j += 4) {
            float4 h4 = *(const float4*)&h_s[j];
            acc += w[j] * h4.x + w[j + 1] * h4.y + w[j + 2] * h4.z + w[j + 3] * h4.w;
        }
        #pragma unroll
        for (int j = 0; j < 64; j += 4) {
            float4 h4 = *(const float4*)&h_s[64 + j];
            acc += Wsm[j * 512 + r] * h4.x + Wsm[(j + 1) * 512 + r] * h4.y
                 + Wsm[(j + 2) * 512 + r] * h4.z + Wsm[(j + 3) * 512 + r] * h4.w;
        }
        g_s[r] = acc;
        __syncthreads();
        if (r < 128) {
            float iv = sigm(g_s[r]);
            float fv = sigm(g_s[128 + r]);
            float gv = tanh_f(g_s[256 + r]);
            float ov = sigm(g_s[384 + r]);
            cv = fv * cv + iv * gv;
            float hv = ov * tanh_f(cv);
            h_s[r] = hv;
            hr[t * 128 + r] = hv;
        }
        __syncthreads();
    }
}

// ---------------- instant layernorm over last dim (256) ----------------
__global__ void iln_kernel(const float* __restrict__ enc, const float* __restrict__ gamma,
                           const float* __restrict__ beta, float* __restrict__ out) {
    int bt = blockIdx.x, tid = threadIdx.x;
    float v = enc[(size_t)bt * ENCD + tid];
    float s1 = v, s2 = v * v;
    #pragma unroll
    for (int o = 16; o > 0; o >>= 1) {
        s1 += __shfl_xor_sync(0xffffffff, s1, o);
        s2 += __shfl_xor_sync(0xffffffff, s2, o);
    }
    __shared__ float r1[8], r2[8];
    int wid = tid >> 5;
    if ((tid & 31) == 0) { r1[wid] = s1; r2[wid] = s2; }
    __syncthreads();
    if (tid == 0) {
        float a1 = 0.0f, a2 = 0.0f;
        #pragma unroll
        for (int i = 0; i < 8; i++) { a1 += r1[i]; a2 += r2[i]; }
        r1[0] = a1; r2[0] = a2;
    }
    __syncthreads();
    float mean = r1[0] * (1.0f / 256.0f);
    float var  = r2[0] * (1.0f / 256.0f) - mean * mean;
    out[(size_t)bt * ENCD + tid] =
        (v - mean) * rsqrtf(var + 1e-7f) * gamma[tid] + beta[tid];
}

// ---------------- overlap-add ----------------
__global__ void ola_kernel(const float* __restrict__ dec, float* __restrict__ out) {
    int s = blockIdx.x * 256 + threadIdx.x;
    int b = blockIdx.y;
    int thi = min(TT - 1, s >> 8);
    int tlo = (s >= 1024) ? ((s - 1023 + 255) >> 8) : 0;
    float acc = 0.0f;
    for (int t = tlo; t <= thi; t++)
        acc += dec[((size_t)b * TT + t) * 1024 + (s - (t << 8))];
    out[(size_t)b * NSAMP + s] = acc;
}

// ---------------- host ----------------
extern "C" void kernel_launch(void* const* d_in, const int* in_sizes, int n_in,
                              void* d_out, int out_size) {
    const float* x        = (const float*)d_in[0];
    const float* st1      = (const float*)d_in[1];
    const float* st2      = (const float*)d_in[2];
    const float* s1_Wih1  = (const float*)d_in[3];
    const float* s1_Whh1  = (const float*)d_in[4];
    const float* s1_bih1  = (const float*)d_in[5];
    const float* s1_bhh1  = (const float*)d_in[6];
    const float* s1_Wih2  = (const float*)d_in[7];
    const float* s1_Whh2  = (const float*)d_in[8];
    const float* s1_bih2  = (const float*)d_in[9];
    const float* s1_bhh2  = (const float*)d_in[10];
    const float* s1_Wd    = (const float*)d_in[11];
    const float* s1_bd    = (const float*)d_in[12];
    const float* s2_Wih1  = (const float*)d_in[13];
    const float* s2_Whh1  = (const float*)d_in[14];
    const float* s2_bih1  = (const float*)d_in[15];
    const float* s2_bhh1  = (const float*)d_in[16];
    const float* s2_Wih2  = (const float*)d_in[17];
    const float* s2_Whh2  = (const float*)d_in[18];
    const float* s2_bih2  = (const float*)d_in[19];
    const float* s2_bhh2  = (const float*)d_in[20];
    const float* s2_Wd    = (const float*)d_in[21];
    const float* s2_bd    = (const float*)d_in[22];
    const float* enc_W    = (const float*)d_in[23];
    const float* dec_W    = (const float*)d_in[24];
    const float* gamma    = (const float*)d_in[25];
    const float* beta     = (const float*)d_in[26];
    float* out = (float*)d_out;

    float *mag, *Rm, *Imb, *xg, *h1, *h2, *mask1, *y1, *enc, *encn, *m2e, *dec, *w1p;
    cudaGetSymbolAddress((void**)&mag,   g_mag);
    cudaGetSymbolAddress((void**)&Rm,    g_Rm);
    cudaGetSymbolAddress((void**)&Imb,   g_Imb);
    cudaGetSymbolAddress((void**)&xg,    g_xg);
    cudaGetSymbolAddress((void**)&h1,    g_h1);
    cudaGetSymbolAddress((void**)&h2,    g_h2);
    cudaGetSymbolAddress((void**)&mask1, g_mask1);
    cudaGetSymbolAddress((void**)&y1,    g_y1);
    cudaGetSymbolAddress((void**)&enc,   g_enc);
    cudaGetSymbolAddress((void**)&encn,  g_encn);
    cudaGetSymbolAddress((void**)&m2e,   g_m2e);
    cudaGetSymbolAddress((void**)&dec,   g_dec);
    cudaGetSymbolAddress((void**)&w1p,   g_w1p);

    const int LSTM_SMEM = (64 * 512 + 128 + 512) * 4;  // 133,632 B
    cudaFuncSetAttribute(lstm_kernel, cudaFuncAttributeMaxDynamicSharedMemorySize, LSTM_SMEM);

    const int MT = (BT + 127) / 128;  // 499

    // ---- STFT + weight pack ----
    stft_kernel<<<BT, 256>>>(x, mag, Rm, Imb);
    pack_w1<<<(512 * MAGP + 255) / 256, 256>>>(s1_Wih1, w1p);

    // ---- separation block 1 (on magnitude) ----
    gemm_mma<0><<<dim3(MT, 4), 256>>>(mag, w1p, s1_bih1, s1_bhh1, nullptr, xg,
                                      BT, 512, MAGP, MAGP, MAGP, 512);
    lstm_kernel<<<BATCH, 512, LSTM_SMEM>>>(xg, h1, s1_Whh1, st1, 0);
    gemm_mma<0><<<dim3(MT, 4), 256>>>(h1, s1_Wih2, s1_bih2, s1_bhh2, nullptr, xg,
                                      BT, 512, 128, 128, 128, 512);
    lstm_kernel<<<BATCH, 512, LSTM_SMEM>>>(xg, h2, s1_Whh2, st1, 1);
    gemm_mma<1><<<dim3(MT, 5), 256>>>(h2, s1_Wd, s1_bd, nullptr, nullptr, mask1,
                                      BT, NFREQ, 128, 128, 128, NFREQ);

    // ---- masked iSTFT ----
    ifft_kernel<<<BT, 256>>>(mask1, Rm, Imb, y1);

    // ---- encoder + instant LN ----
    gemm_mma<0><<<dim3(MT, 2), 256>>>(y1, enc_W, nullptr, nullptr, nullptr, enc,
                                      BT, ENCD, 1024, 1024, 1024, ENCD);
    iln_kernel<<<BT, 256>>>(enc, gamma, beta, encn);

    // ---- separation block 2 ----
    gemm_mma<0><<<dim3(MT, 4), 256>>>(encn, s2_Wih1, s2_bih1, s2_bhh1, nullptr, xg,
                                      BT, 512, ENCD, ENCD, ENCD, 512);
    lstm_kernel<<<BATCH, 512, LSTM_SMEM>>>(xg, h1, s2_Whh1, st2, 0);
    gemm_mma<0><<<dim3(MT, 4), 256>>>(h1, s2_Wih2, s2_bih2, s2_bhh2, nullptr, xg,
                                      BT, 512, 128, 128, 128, 512);
    lstm_kernel<<<BATCH, 512, LSTM_SMEM>>>(xg, h2, s2_Whh2, st2, 1);
    gemm_mma<2><<<dim3(MT, 2), 256>>>(h2, s2_Wd, s2_bd, nullptr, enc, m2e,
                                      BT, ENCD, 128, 128, 128, ENCD);

    // ---- decoder + overlap-add ----
    gemm_mma<0><<<dim3(MT, 8), 256>>>(m2e, dec_W, nullptr, nullptr, nullptr, dec,
                                      BT, 1024, ENCD, ENCD, ENCD, 1024);
    ola_kernel<<<dim3(NSAMP / 256, BATCH), 256>>>(dec, out);
}

// round 7
// speedup vs baseline: 1.3882x; 1.1332x over previous
#include <cuda_runtime.h>
#include <cstdint>

#define NSAMP 256000
#define BATCH 64
#define TT 997
#define BT (BATCH * TT)   // 63808
#define NFREQ 513
#define MAGP 528          // mag padded stride (33*16)
#define ENCD 256
#define EPS32 1.1920928955078125e-07f
#define PI_F 3.14159265358979323846f

// ---------------- scratch (device globals; allocation-free rule) ----------------
__device__ float g_mag [(size_t)BT * MAGP];
__device__ float g_Rm  [(size_t)BT * NFREQ];
__device__ float g_Imb [(size_t)BT * NFREQ];
__device__ float g_xg  [(size_t)BT * 512];
__device__ float g_h1  [(size_t)BT * 128];
__device__ float g_h2  [(size_t)BT * 128];
__device__ float g_mask1[(size_t)BT * NFREQ];
__device__ float g_y1  [(size_t)BT * 1024];
__device__ float g_enc [(size_t)BT * ENCD];
__device__ float g_encn[(size_t)BT * ENCD];
__device__ float g_m2e [(size_t)BT * ENCD];
__device__ float g_dec [(size_t)BT * 1024];
__device__ float g_w1p [512 * MAGP];

__device__ __forceinline__ float sigm(float x) { return 1.0f / (1.0f + __expf(-x)); }
__device__ __forceinline__ float tanh_f(float x) { return 2.0f / (1.0f + __expf(-2.0f * x)) - 1.0f; }

// ---------------- cp.async helpers ----------------
__device__ __forceinline__ void cp16(uint32_t dst, const void* src) {
    asm volatile("cp.async.cg.shared.global [%0], [%1], 16;" :: "r"(dst), "l"(src));
}
#define CP_COMMIT() asm volatile("cp.async.commit_group;" ::: "memory")
#define CP_WAIT(n)  asm volatile("cp.async.wait_group %0;" :: "n"(n) : "memory")

// ---------------- 3xTF32 split: f = hi + lo, both tf32 (rna) ----------------
__device__ __forceinline__ void tf32split(float f, uint32_t& hi, uint32_t& lo) {
    uint32_t h;
    asm("cvt.rna.tf32.f32 %0, %1;" : "=r"(h) : "f"(f));
    float r = f - __uint_as_float(h);
    asm("cvt.rna.tf32.f32 %0, %1;" : "=r"(lo) : "f"(r));
    hi = h;
}
__device__ __forceinline__ void mma8(float* c, const uint32_t* a, const uint32_t* b) {
    asm volatile(
        "mma.sync.aligned.m16n8k8.row.col.f32.tf32.tf32.f32 "
        "{%0,%1,%2,%3}, {%4,%5,%6,%7}, {%8,%9}, {%0,%1,%2,%3};"
        : "+f"(c[0]), "+f"(c[1]), "+f"(c[2]), "+f"(c[3])
        : "r"(a[0]), "r"(a[1]), "r"(a[2]), "r"(a[3]), "r"(b[0]), "r"(b[1]));
}

// ---------------- 3xTF32 tensor-core GEMM: C[M,N] = A[M,K] @ W[N,K]^T ----------------
// MODE 0: + b1 + b2 (nullable). MODE 1: sigmoid(+b1). MODE 2: sigmoid(+b1)*aux[m,n].
// Tile 128x128x16, 8 warps (4x2), warp tile 32x64, mma.m16n8k8 tf32 x3 (error comp).
// Requires K % 16 == 0.
#define SSTRIDE 20   // floats per smem row (conflict-free for quad pattern + 16B aligned)
template<int MODE>
__global__ void __launch_bounds__(256) gemm_mma(
    const float* __restrict__ A, const float* __restrict__ W,
    const float* __restrict__ b1, const float* __restrict__ b2,
    const float* __restrict__ aux, float* __restrict__ C,
    int M, int N, int K, int lda, int ldw, int ldc)
{
    __shared__ float As[2][128 * SSTRIDE];
    __shared__ float Bs[2][128 * SSTRIDE];
    int tid = threadIdx.x;
    int lane = tid & 31;
    int wid = tid >> 5;
    int wm = wid & 3;           // warp row (4)
    int wn = wid >> 2;          // warp col (2)
    int m0 = blockIdx.x * 128, n0 = blockIdx.y * 128;

    // loader mapping: row = tid/2, two 16B chunks at (tid&1)*2 + {0,1}
    int lr = tid >> 1;
    int lc0 = (tid & 1) * 2;
    const float* Arow = A + (size_t)min(m0 + lr, M - 1) * lda;
    const float* Wrow = W + (size_t)min(n0 + lr, N - 1) * ldw;

    uint32_t sA0 = (uint32_t)__cvta_generic_to_shared(&As[0][0]);
    uint32_t sB0 = (uint32_t)__cvta_generic_to_shared(&Bs[0][0]);
    const uint32_t stageBytes = 128 * SSTRIDE * 4;
    uint32_t dstOffA = (lr * SSTRIDE + lc0 * 4) * 4;

    #define LOAD_STAGE(t, s) do { \
        uint32_t dA = sA0 + (s) * stageBytes + dstOffA; \
        uint32_t dB = sB0 + (s) * stageBytes + dstOffA; \
        int f0 = (t) * 16 + lc0 * 4; \
        cp16(dA,      Arow + f0); \
        cp16(dA + 16, Arow + f0 + 4); \
        cp16(dB,      Wrow + f0); \
        cp16(dB + 16, Wrow + f0 + 4); \
        CP_COMMIT(); \
    } while (0)

    float c[2][8][4];
    #pragma unroll
    for (int mi = 0; mi < 2; mi++)
        #pragma unroll
        for (int j = 0; j < 8; j++)
            #pragma unroll
            for (int r = 0; r < 4; r++) c[mi][j][r] = 0.0f;

    const int NT = K >> 4;
    LOAD_STAGE(0, 0);

    // fragment base offsets (floats)
    int aoff0 = (wm * 32 + (lane >> 2)) * SSTRIDE + (lane & 3);
    int boff0 = (wn * 64 + (lane >> 2)) * SSTRIDE + (lane & 3);

    for (int t = 0; t < NT; t++) {
        int buf = t & 1;
        if (t + 1 < NT) {
            LOAD_STAGE(t + 1, (t + 1) & 1);
            CP_WAIT(1);
        } else {
            CP_WAIT(0);
        }
        __syncthreads();

        const float* Sa = As[buf];
        const float* Sb = Bs[buf];
        #pragma unroll
        for (int kh = 0; kh < 2; kh++) {
            uint32_t ah[2][4], al[2][4];
            #pragma unroll
            for (int mi = 0; mi < 2; mi++) {
                int o = aoff0 + mi * 16 * SSTRIDE + kh * 8;
                tf32split(Sa[o],                   ah[mi][0], al[mi][0]);
                tf32split(Sa[o + 8 * SSTRIDE],     ah[mi][1], al[mi][1]);
                tf32split(Sa[o + 4],               ah[mi][2], al[mi][2]);
                tf32split(Sa[o + 8 * SSTRIDE + 4], ah[mi][3], al[mi][3]);
            }
            uint32_t bh[8][2], bl[8][2];
            #pragma unroll
            for (int j = 0; j < 8; j++) {
                int o = boff0 + j * 8 * SSTRIDE + kh * 8;
                tf32split(Sb[o],     bh[j][0], bl[j][0]);
                tf32split(Sb[o + 4], bh[j][1], bl[j][1]);
            }
            #pragma unroll
            for (int mi = 0; mi < 2; mi++)
                #pragma unroll
                for (int j = 0; j < 8; j++) {
                    mma8(c[mi][j], ah[mi], bl[j]);   // hi*lo
                    mma8(c[mi][j], al[mi], bh[j]);   // lo*hi
                    mma8(c[mi][j], ah[mi], bh[j]);   // hi*hi
                }
        }
        __syncthreads();
    }

    // epilogue: c0/c1 -> (row, 2q), (row, 2q+1); c2/c3 -> row+8
    #pragma unroll
    for (int mi = 0; mi < 2; mi++) {
        #pragma unroll
        for (int rh = 0; rh < 2; rh++) {
            int m = m0 + wm * 32 + mi * 16 + (lane >> 2) + rh * 8;
            if (m >= M) continue;
            float* crow = C + (size_t)m * ldc;
            const float* arow = (MODE == 2) ? aux + (size_t)m * ldc : nullptr;
            #pragma unroll
            for (int j = 0; j < 8; j++) {
                int n = n0 + wn * 64 + j * 8 + 2 * (lane & 3);
                float v0 = c[mi][j][rh * 2];
                float v1 = c[mi][j][rh * 2 + 1];
                if (MODE == 0) {
                    if (b1) { v0 += __ldg(&b1[n]); v1 += __ldg(&b1[n + 1]); }
                    if (b2) { v0 += __ldg(&b2[n]); v1 += __ldg(&b2[n + 1]); }
                    if (n < N)     crow[n]     = v0;
                    if (n + 1 < N) crow[n + 1] = v1;
                } else if (MODE == 1) {
                    if (n < N)     crow[n]     = sigm(v0 + __ldg(&b1[n]));
                    if (n + 1 < N) crow[n + 1] = sigm(v1 + __ldg(&b1[n + 1]));
                } else {
                    if (n < N)     crow[n]     = sigm(v0 + __ldg(&b1[n]))     * arow[n];
                    if (n + 1 < N) crow[n + 1] = sigm(v1 + __ldg(&b1[n + 1])) * arow[n + 1];
                }
            }
        }
    }
    #undef LOAD_STAGE
}

// ---------------- weight pack: s1_Wih1 [512,513] -> [512,528] zero-padded ----------------
__global__ void pack_w1(const float* __restrict__ w, float* __restrict__ out) {
    int i = blockIdx.x * 256 + threadIdx.x;
    if (i < 512 * MAGP) {
        int r = i / MAGP, c = i - r * MAGP;
        out[i] = (c < NFREQ) ? w[r * NFREQ + c] : 0.0f;
    }
}

// ---------------- 512-pt complex Stockham FFT in shared memory ----------------
__device__ __forceinline__ float2* fft512(float2* a, float2* b, float sign, int tid) {
    float2* src = a; float2* dst = b;
    #pragma unroll
    for (int s = 0; s < 9; s++) {
        int m = 1 << s;
        int l = 256 >> s;
        int j = tid >> s;
        int k = tid & (m - 1);
        float coef = sign * PI_F / (float)l;
        float2 c0 = src[tid];
        float2 c1 = src[tid + 256];
        float ws, wc;
        __sincosf(coef * (float)j, &ws, &wc);
        float2 dif = make_float2(c0.x - c1.x, c0.y - c1.y);
        dst[2 * j * m + k]     = make_float2(c0.x + c1.x, c0.y + c1.y);
        dst[2 * j * m + k + m] = make_float2(wc * dif.x - ws * dif.y, wc * dif.y + ws * dif.x);
        __syncthreads();
        float2* t = src; src = dst; dst = t;
    }
    return src;
}

// ---------------- STFT: frames -> mag (stride MAGP, zero-padded), Rm, Im ----------------
__global__ void stft_kernel(const float* __restrict__ x, float* __restrict__ mag,
                            float* __restrict__ Rm, float* __restrict__ Imb) {
    __shared__ float2 za[512], zb[512];
    int bt = blockIdx.x;
    int b = bt / TT, t = bt - b * TT;
    const float* xp = x + (size_t)b * NSAMP + t * 256;
    int tid = threadIdx.x;
    for (int n = tid; n < 512; n += 256) {
        float w0 = 0.5f * (1.0f - cospif((float)(2 * n)     * (1.0f / 512.0f)));
        float w1 = 0.5f * (1.0f - cospif((float)(2 * n + 1) * (1.0f / 512.0f)));
        za[n] = make_float2(xp[2 * n] * w0, xp[2 * n + 1] * w1);
    }
    __syncthreads();
    float2* Z = fft512(za, zb, -1.0f, tid);
    size_t baseM = (size_t)bt * MAGP;
    size_t base = (size_t)bt * NFREQ;
    for (int k = tid; k <= 512; k += 256) {
        float2 zk = Z[k & 511];
        float2 zc = Z[(512 - k) & 511];
        float Er = 0.5f * (zk.x + zc.x), Ei = 0.5f * (zk.y - zc.y);
        float Or = 0.5f * (zk.y + zc.y), Oi = -0.5f * (zk.x - zc.x);
        float ws, wc;
        __sincosf(-PI_F * (float)k * (1.0f / 512.0f), &ws, &wc);
        float Xr = Er + wc * Or - ws * Oi;
        float Xi = Ei + wc * Oi + ws * Or;
        float mg = sqrtf(fmaxf(Xr * Xr + Xi * Xi, EPS32));
        float rp = Xr + EPS32, ip = Xi + EPS32;
        float inv = rsqrtf(rp * rp + ip * ip);
        mag[baseM + k] = mg;
        Rm[base + k]   = mg * rp * inv;
        Imb[base + k]  = mg * ip * inv;
    }
    if (tid < MAGP - NFREQ) mag[baseM + NFREQ + tid] = 0.0f;  // zero K padding
}

// ---------------- masked iSTFT ----------------
__global__ void ifft_kernel(const float* __restrict__ mask, const float* __restrict__ Rm,
                            const float* __restrict__ Imb, float* __restrict__ y) {
    __shared__ float2 Xs[513];
    __shared__ float2 za[512], zb[512];
    int bt = blockIdx.x;
    int tid = threadIdx.x;
    size_t base = (size_t)bt * NFREQ;
    for (int k = tid; k <= 512; k += 256) {
        float mk = mask[base + k];
        Xs[k] = make_float2(mk * Rm[base + k], mk * Imb[base + k]);
    }
    __syncthreads();
    for (int k = tid; k < 512; k += 256) {
        float2 xk = Xs[k];
        float2 xc = Xs[512 - k];
        float Ar = 0.5f * (xk.x + xc.x), Ai = 0.5f * (xk.y - xc.y);
        float Br = 0.5f * (xk.x - xc.x), Bi = 0.5f * (xk.y + xc.y);
        float ws, wc;
        __sincosf(PI_F * (float)k * (1.0f / 512.0f), &ws, &wc);
        float B2r = wc * Br - ws * Bi;
        float B2i = wc * Bi + ws * Br;
        za[k] = make_float2(Ar - B2i, Ai + B2r);
    }
    __syncthreads();
    float2* Zr = fft512(za, zb, 1.0f, tid);
    float* yp = y + (size_t)bt * 1024;
    const float scale = 1.0f / 512.0f;
    for (int n = tid; n < 512; n += 256) {
        yp[2 * n]     = Zr[n].x * scale;
        yp[2 * n + 1] = Zr[n].y * scale;
    }
}

// ---------------- LSTM scan: one CTA per batch elem, thread r = gate row r ----------------
// Whh cols 0..63 in registers; cols 64..127 in smem as float4 groups [16][512].
// 4 accumulators (ILP), x prefetch, per-thread gate nonlinearity before barrier.
__global__ void __launch_bounds__(512) lstm_kernel(
    const float* __restrict__ xg, float* __restrict__ hout,
    const float* __restrict__ Whh, const float* __restrict__ state, int layer) {
    extern __shared__ float sm[];
    float4* Wsm4 = (float4*)sm;            // [16][512] float4
    float*  h_s  = sm + 16 * 512 * 4;      // 128 floats (16B aligned)
    float*  g_s  = h_s + 128;              // 512
    int b = blockIdx.x, r = threadIdx.x;
    float w[64];
    #pragma unroll
    for (int j = 0; j < 64; j++) w[j] = Whh[r * 128 + j];
    #pragma unroll
    for (int g = 0; g < 16; g++) {
        const float* p = Whh + r * 128 + 64 + g * 4;
        Wsm4[g * 512 + r] = make_float4(p[0], p[1], p[2], p[3]);
    }
    float cv = 0.0f;
    if (r < 128) {
        size_t sb = ((size_t)(layer * BATCH + b) * 128 + r) * 2;
        h_s[r] = state[sb];
        cv     = state[sb + 1];
    }
    __syncthreads();
    const float* xr = xg + (size_t)b * TT * 512 + r;
    float* hr = hout + (size_t)b * TT * 128;
    bool is_tanh_gate = (r >= 256) && (r < 384);
    float xcur = xr[0];
    for (int t = 0; t < TT; t++) {
        float xnext = (t + 1 < TT) ? __ldg(xr + (t + 1) * 512) : 0.0f;
        const float4* h4 = (const float4*)h_s;
        float a0 = xcur, a1 = 0.0f, a2 = 0.0f, a3 = 0.0f;
        #pragma unroll
        for (int g = 0; g < 16; g++) {
            float4 hv = h4[g];
            a0 += w[4 * g]     * hv.x;
            a1 += w[4 * g + 1] * hv.y;
            a2 += w[4 * g + 2] * hv.z;
            a3 += w[4 * g + 3] * hv.w;
        }
        #pragma unroll
        for (int g = 0; g < 16; g++) {
            float4 wv = Wsm4[g * 512 + r];
            float4 hv = h4[16 + g];
            a0 += wv.x * hv.x;
            a1 += wv.y * hv.y;
            a2 += wv.z * hv.z;
            a3 += wv.w * hv.w;
        }
        float acc = (a0 + a1) + (a2 + a3);
        g_s[r] = is_tanh_gate ? tanh_f(acc) : sigm(acc);
        __syncthreads();
        if (r < 128) {
            float iv = g_s[r];
            float fv = g_s[128 + r];
            float gv = g_s[256 + r];
            float ov = g_s[384 + r];
            cv = fv * cv + iv * gv;
            float hv = ov * tanh_f(cv);
            h_s[r] = hv;
            hr[t * 128 + r] = hv;
        }
        __syncthreads();
        xcur = xnext;
    }
}

// ---------------- instant layernorm over last dim (256) ----------------
__global__ void iln_kernel(const float* __restrict__ enc, const float* __restrict__ gamma,
                           const float* __restrict__ beta, float* __restrict__ out) {
    int bt = blockIdx.x, tid = threadIdx.x;
    float v = enc[(size_t)bt * ENCD + tid];
    float s1 = v, s2 = v * v;
    #pragma unroll
    for (int o = 16; o > 0; o >>= 1) {
        s1 += __shfl_xor_sync(0xffffffff, s1, o);
        s2 += __shfl_xor_sync(0xffffffff, s2, o);
    }
    __shared__ float r1[8], r2[8];
    int wid = tid >> 5;
    if ((tid & 31) == 0) { r1[wid] = s1; r2[wid] = s2; }
    __syncthreads();
    if (tid == 0) {
        float a1 = 0.0f, a2 = 0.0f;
        #pragma unroll
        for (int i = 0; i < 8; i++) { a1 += r1[i]; a2 += r2[i]; }
        r1[0] = a1; r2[0] = a2;
    }
    __syncthreads();
    float mean = r1[0] * (1.0f / 256.0f);
    float var  = r2[0] * (1.0f / 256.0f) - mean * mean;
    out[(size_t)bt * ENCD + tid] =
        (v - mean) * rsqrtf(var + 1e-7f) * gamma[tid] + beta[tid];
}

// ---------------- overlap-add ----------------
__global__ void ola_kernel(const float* __restrict__ dec, float* __restrict__ out) {
    int s = blockIdx.x * 256 + threadIdx.x;
    int b = blockIdx.y;
    int thi = min(TT - 1, s >> 8);
    int tlo = (s >= 1024) ? ((s - 1023 + 255) >> 8) : 0;
    float acc = 0.0f;
    for (int t = tlo; t <= thi; t++)
        acc += dec[((size_t)b * TT + t) * 1024 + (s - (t << 8))];
    out[(size_t)b * NSAMP + s] = acc;
}

// ---------------- host ----------------
extern "C" void kernel_launch(void* const* d_in, const int* in_sizes, int n_in,
                              void* d_out, int out_size) {
    const float* x        = (const float*)d_in[0];
    const float* st1      = (const float*)d_in[1];
    const float* st2      = (const float*)d_in[2];
    const float* s1_Wih1  = (const float*)d_in[3];
    const float* s1_Whh1  = (const float*)d_in[4];
    const float* s1_bih1  = (const float*)d_in[5];
    const float* s1_bhh1  = (const float*)d_in[6];
    const float* s1_Wih2  = (const float*)d_in[7];
    const float* s1_Whh2  = (const float*)d_in[8];
    const float* s1_bih2  = (const float*)d_in[9];
    const float* s1_bhh2  = (const float*)d_in[10];
    const float* s1_Wd    = (const float*)d_in[11];
    const float* s1_bd    = (const float*)d_in[12];
    const float* s2_Wih1  = (const float*)d_in[13];
    const float* s2_Whh1  = (const float*)d_in[14];
    const float* s2_bih1  = (const float*)d_in[15];
    const float* s2_bhh1  = (const float*)d_in[16];
    const float* s2_Wih2  = (const float*)d_in[17];
    const float* s2_Whh2  = (const float*)d_in[18];
    const float* s2_bih2  = (const float*)d_in[19];
    const float* s2_bhh2  = (const float*)d_in[20];
    const float* s2_Wd    = (const float*)d_in[21];
    const float* s2_bd    = (const float*)d_in[22];
    const float* enc_W    = (const float*)d_in[23];
    const float* dec_W    = (const float*)d_in[24];
    const float* gamma    = (const float*)d_in[25];
    const float* beta     = (const float*)d_in[26];
    float* out = (float*)d_out;

    float *mag, *Rm, *Imb, *xg, *h1, *h2, *mask1, *y1, *enc, *encn, *m2e, *dec, *w1p;
    cudaGetSymbolAddress((void**)&mag,   g_mag);
    cudaGetSymbolAddress((void**)&Rm,    g_Rm);
    cudaGetSymbolAddress((void**)&Imb,   g_Imb);
    cudaGetSymbolAddress((void**)&xg,    g_xg);
    cudaGetSymbolAddress((void**)&h1,    g_h1);
    cudaGetSymbolAddress((void**)&h2,    g_h2);
    cudaGetSymbolAddress((void**)&mask1, g_mask1);
    cudaGetSymbolAddress((void**)&y1,    g_y1);
    cudaGetSymbolAddress((void**)&enc,   g_enc);
    cudaGetSymbolAddress((void**)&encn,  g_encn);
    cudaGetSymbolAddress((void**)&m2e,   g_m2e);
    cudaGetSymbolAddress((void**)&dec,   g_dec);
    cudaGetSymbolAddress((void**)&w1p,   g_w1p);

    const int LSTM_SMEM = (16 * 512 * 4 + 128 + 512) * 4;  // 133,632 B
    cudaFuncSetAttribute(lstm_kernel, cudaFuncAttributeMaxDynamicSharedMemorySize, LSTM_SMEM);

    const int MT = (BT + 127) / 128;  // 499

    // ---- STFT + weight pack (pack launched twice -> ncu -s 5 lands on a GEMM) ----
    stft_kernel<<<BT, 256>>>(x, mag, Rm, Imb);
    pack_w1<<<(512 * MAGP + 255) / 256, 256>>>(s1_Wih1, w1p);
    pack_w1<<<(512 * MAGP + 255) / 256, 256>>>(s1_Wih1, w1p);

    // ---- separation block 1 (on magnitude) ----
    gemm_mma<0><<<dim3(MT, 4), 256>>>(mag, w1p, s1_bih1, s1_bhh1, nullptr, xg,
                                      BT, 512, MAGP, MAGP, MAGP, 512);
    lstm_kernel<<<BATCH, 512, LSTM_SMEM>>>(xg, h1, s1_Whh1, st1, 0);
    gemm_mma<0><<<dim3(MT, 4), 256>>>(h1, s1_Wih2, s1_bih2, s1_bhh2, nullptr, xg,
                                      BT, 512, 128, 128, 128, 512);
    lstm_kernel<<<BATCH, 512, LSTM_SMEM>>>(xg, h2, s1_Whh2, st1, 1);
    gemm_mma<1><<<dim3(MT, 5), 256>>>(h2, s1_Wd, s1_bd, nullptr, nullptr, mask1,
                                      BT, NFREQ, 128, 128, 128, NFREQ);

    // ---- masked iSTFT ----
    ifft_kernel<<<BT, 256>>>(mask1, Rm, Imb, y1);

    // ---- encoder + instant LN ----
    gemm_mma<0><<<dim3(MT, 2), 256>>>(y1, enc_W, nullptr, nullptr, nullptr, enc,
                                      BT, ENCD, 1024, 1024, 1024, ENCD);
    iln_kernel<<<BT, 256>>>(enc, gamma, beta, encn);

    // ---- separation block 2 ----
    gemm_mma<0><<<dim3(MT, 4), 256>>>(encn, s2_Wih1, s2_bih1, s2_bhh1, nullptr, xg,
                                      BT, 512, ENCD, ENCD, ENCD, 512);
    lstm_kernel<<<BATCH, 512, LSTM_SMEM>>>(xg, h1, s2_Whh1, st2, 0);
    gemm_mma<0><<<dim3(MT, 4), 256>>>(h1, s2_Wih2, s2_bih2, s2_bhh2, nullptr, xg,
                                      BT, 512, 128, 128, 128, 512);
    lstm_kernel<<<BATCH, 512, LSTM_SMEM>>>(xg, h2, s2_Whh2, st2, 1);
    gemm_mma<2><<<dim3(MT, 2), 256>>>(h2, s2_Wd, s2_bd, nullptr, enc, m2e,
                                      BT, ENCD, 128, 128, 128, ENCD);

    // ---- decoder + overlap-add ----
    gemm_mma<0><<<dim3(MT, 8), 256>>>(m2e, dec_W, nullptr, nullptr, nullptr, dec,
                                      BT, 1024, ENCD, ENCD, ENCD, 1024);
    ola_kernel<<<dim3(NSAMP / 256, BATCH), 256>>>(dec, out);
}